// round 16
// baseline (speedup 1.0000x reference)
#include <cuda_runtime.h>
#include <cuda_bf16.h>
#include <cstdint>

#define SEQ   2048
#define EMB   1024
#define NHEAD 64
#define BATCH 8
#define ROWS  (BATCH*SEQ)   // 16384

// Split-bf16 scratch (allocation-free device globals, 16B-aligned for cp.async).
// q/k: [row][64] as u32 pairs. v: transposed per 64-row block.
__device__ __align__(16) uint32_t      g_qh[(size_t)ROWS * 32], g_ql[(size_t)ROWS * 32];
__device__ __align__(16) uint32_t      g_kh[(size_t)ROWS * 32], g_kl[(size_t)ROWS * 32];
__device__ __align__(16) __nv_bfloat16 g_vth[(size_t)ROWS * 64], g_vtl[(size_t)ROWS * 64];
// Pre-split weights, chunk-tiled: [chunk c][row r][kk], r<192 = hi(n=r),
// r>=192 = lo(n=r-192). n: 0-63 Q (QSCALE folded), 64-127 K, 128-191 V.
__device__ __align__(16) __nv_bfloat16 g_wsp[(size_t)32 * 384 * 32];

#define QSCALE 0.1803368801111243f   // 0.125 * log2(e): base-2 softmax

// ---------------------------------------------------------------------------
// Helpers
// ---------------------------------------------------------------------------
__device__ __forceinline__ void split2(float vx, float vy,
                                       uint32_t& hi, uint32_t& lo)
{
    __nv_bfloat16 hx = __float2bfloat16(vx);
    __nv_bfloat16 hy = __float2bfloat16(vy);
    __nv_bfloat16 lx = __float2bfloat16(vx - __bfloat162float(hx));
    __nv_bfloat16 ly = __float2bfloat16(vy - __bfloat162float(hy));
    hi = ((uint32_t)__bfloat16_as_ushort(hy) << 16) | __bfloat16_as_ushort(hx);
    lo = ((uint32_t)__bfloat16_as_ushort(ly) << 16) | __bfloat16_as_ushort(lx);
}

__device__ __forceinline__ void mma_bf16(float* c, const uint32_t* a,
                                         const uint32_t* b)
{
    asm volatile(
        "mma.sync.aligned.m16n8k16.row.col.f32.bf16.bf16.f32 "
        "{%0,%1,%2,%3}, {%4,%5,%6,%7}, {%8,%9}, {%0,%1,%2,%3};"
        : "+f"(c[0]), "+f"(c[1]), "+f"(c[2]), "+f"(c[3])
        : "r"(a[0]), "r"(a[1]), "r"(a[2]), "r"(a[3]), "r"(b[0]), "r"(b[1]));
}

__device__ __forceinline__ float ex2(float x) {
    float y;
    asm("ex2.approx.f32 %0, %1;" : "=f"(y) : "f"(x));
    return y;
}

__device__ __forceinline__ uint32_t pack_hi(float a, float b) {
    return ((uint32_t)__bfloat16_as_ushort(__float2bfloat16(b)) << 16) |
           __bfloat16_as_ushort(__float2bfloat16(a));
}
__device__ __forceinline__ uint32_t pack_lo(float a, float b) {
    float ra = a - __bfloat162float(__float2bfloat16(a));
    float rb = b - __bfloat162float(__float2bfloat16(b));
    return pack_hi(ra, rb);
}

__device__ __forceinline__ uint32_t smem_u32p(const void* p) {
    uint32_t a;
    asm("{ .reg .u64 t; cvta.to.shared.u64 t, %1; cvt.u32.u64 %0, t; }"
        : "=r"(a) : "l"(p));
    return a;
}
__device__ __forceinline__ void cp16(uint32_t dst, const void* src) {
    asm volatile("cp.async.ca.shared.global [%0], [%1], 16;"
                 :: "r"(dst), "l"(src));
}
#define CP_COMMIT()  asm volatile("cp.async.commit_group;" ::: "memory")
#define CP_WAIT(n)   asm volatile("cp.async.wait_group %0;" :: "n"(n) : "memory")

// ---------------------------------------------------------------------------
// Prologue: split W (f32) -> chunk-tiled split-bf16, QSCALE folded into Wq.
// ---------------------------------------------------------------------------
__global__ __launch_bounds__(256) void wsplit_kernel(
    const float* __restrict__ Wk,
    const float* __restrict__ Wq,
    const float* __restrict__ Wv)
{
    int idx = blockIdx.x * 256 + threadIdx.x;   // 0..196607 = (c*32+kk)*192 + n
    int n  = idx % 192;
    int t  = idx / 192;
    int kk = t & 31;
    int c  = t >> 5;
    int k  = c * 32 + kk;
    const float* Wp = (n < 64) ? Wq : ((n < 128) ? Wk : Wv);
    float v = Wp[(size_t)k * NHEAD + (n & 63)];
    if (n < 64) v *= QSCALE;
    __nv_bfloat16 h = __float2bfloat16(v);
    __nv_bfloat16 l = __float2bfloat16(v - __bfloat162float(h));
    g_wsp[((size_t)c * 384 + n) * 32 + kk]       = h;
    g_wsp[((size_t)c * 384 + 192 + n) * 32 + kk] = l;
}

// ---------------------------------------------------------------------------
// QKV projection via mma.sync bf16 (2-term split). M=64/CTA (grid 256),
// N=192 fused, K in 32-wide chunks. x register-prefetched + split in-kernel;
// W pre-split, staged via cp.async double buffer (no per-chunk conversion).
// B smem: rows padded to 40 bf16 (80B) -> 16B-aligned cp.async dsts and
// conflict-free fragment banks (20g+tg mod 32 distinct).
// ---------------------------------------------------------------------------
__global__ __launch_bounds__(256, 2) void qkv_mma_kernel(
    const float* __restrict__ x,
    const float* __restrict__ Wk,
    const float* __restrict__ Wq,
    const float* __restrict__ Wv)
{
    __shared__ __nv_bfloat16 Ah[64 * 36], Al[64 * 36];
    __shared__ __nv_bfloat16 Bsm[2 * 384 * 40];   // 61440 B

    const int tid  = threadIdx.x;
    const int warp = tid >> 5;
    const int lane = tid & 31;
    const int g    = lane >> 2;
    const int tg   = lane & 3;
    const int mg   = warp & 1;        // 32-row half
    const int ng   = warp >> 1;       // 48-col group
    const int m0   = blockIdx.x * 64;

    const uint32_t smB = smem_u32p(Bsm);

    float acc[2][6][4];
    #pragma unroll
    for (int mt = 0; mt < 2; mt++)
        #pragma unroll
        for (int nb = 0; nb < 6; nb++)
            #pragma unroll
            for (int i = 0; i < 4; i++) acc[mt][nb][i] = 0.0f;

    // x register prefetch geometry
    float4 xa[2];
    const int xr  = tid >> 3;
    const int xc4 = (tid & 7) * 4;

    #define LOAD_X(chunk) do {                                                 \
        int k0_ = (chunk) * 32;                                                \
        xa[0] = *(const float4*)(x + (size_t)(m0 + xr) * EMB + k0_ + xc4);     \
        xa[1] = *(const float4*)(x + (size_t)(m0 + xr + 32) * EMB + k0_ + xc4);\
    } while (0)

    // B staging: 384 rows x 64B = 1536 16B-chunks, 6 per thread
    const int br = tid >> 2;          // row 0..63 (plus +64*j)
    const int bp = (tid & 3) * 16;    // 16B part
    #define STAGE_B(chunk, buf) do {                                           \
        const char* src_ = (const char*)g_wsp + (size_t)(chunk) * 384 * 64;    \
        uint32_t d_ = smB + (buf) * 30720;                                     \
        _Pragma("unroll")                                                      \
        for (int j_ = 0; j_ < 6; j_++) {                                       \
            int r_ = br + j_ * 64;                                             \
            cp16(d_ + r_ * 80 + bp, src_ + (size_t)r_ * 64 + bp);              \
        }                                                                      \
    } while (0)

    STAGE_B(0, 0);
    CP_COMMIT();
    LOAD_X(0);

    for (int chunk = 0; chunk < 32; chunk++) {
        __syncthreads();   // prev mma reads of Ah/Al and Bsm[alt] done

        // ---- store staged x regs -> smem (with split) ----
        #pragma unroll
        for (int i = 0; i < 2; i++) {
            int r = xr + i * 32;
            uint32_t h0, l0, h1, l1;
            split2(xa[i].x, xa[i].y, h0, l0);
            split2(xa[i].z, xa[i].w, h1, l1);
            uint32_t off = r * 36 + xc4;
            *(uint32_t*)(Ah + off)     = h0;
            *(uint32_t*)(Ah + off + 2) = h1;
            *(uint32_t*)(Al + off)     = l0;
            *(uint32_t*)(Al + off + 2) = l1;
        }
        if (chunk < 31) {
            STAGE_B(chunk + 1, (chunk + 1) & 1);
            CP_COMMIT();
            CP_WAIT(1);    // B(chunk) arrived
        } else {
            CP_WAIT(0);
        }
        __syncthreads();   // A stores + B(chunk) visible to all

        if (chunk < 31) LOAD_X(chunk + 1);   // overlap with MMAs below

        const __nv_bfloat16* Bb = Bsm + (chunk & 1) * 15360;

        #pragma unroll
        for (int ks = 0; ks < 2; ks++) {
            uint32_t ah[2][4], al2[2][4];
            #pragma unroll
            for (int mt = 0; mt < 2; mt++) {
                int r0 = mg * 32 + mt * 16 + g;
                uint32_t o0 = r0 * 36 + ks * 16 + 2 * tg;   // bf16 index
                uint32_t o1 = o0 + 8 * 36;
                ah[mt][0] = *(const uint32_t*)(Ah + o0);
                ah[mt][1] = *(const uint32_t*)(Ah + o1);
                ah[mt][2] = *(const uint32_t*)(Ah + o0 + 8);
                ah[mt][3] = *(const uint32_t*)(Ah + o1 + 8);
                al2[mt][0] = *(const uint32_t*)(Al + o0);
                al2[mt][1] = *(const uint32_t*)(Al + o1);
                al2[mt][2] = *(const uint32_t*)(Al + o0 + 8);
                al2[mt][3] = *(const uint32_t*)(Al + o1 + 8);
            }
            #pragma unroll
            for (int nb = 0; nb < 6; nb++) {
                int n = ng * 48 + nb * 8 + g;
                uint32_t obh = n * 40 + ks * 16 + 2 * tg;          // hi row
                uint32_t obl = obh + 192 * 40;                      // lo row
                uint32_t bh[2], bl[2];
                bh[0] = *(const uint32_t*)(Bb + obh);
                bh[1] = *(const uint32_t*)(Bb + obh + 8);
                bl[0] = *(const uint32_t*)(Bb + obl);
                bl[1] = *(const uint32_t*)(Bb + obl + 8);
                #pragma unroll
                for (int mt = 0; mt < 2; mt++) {
                    mma_bf16(acc[mt][nb], ah[mt], bh);
                    mma_bf16(acc[mt][nb], ah[mt], bl);
                    mma_bf16(acc[mt][nb], al2[mt], bh);
                }
            }
        }
    }

    // ---- epilogue: write split-bf16 q/k (row-major) and v (transposed) ----
    const int b_  = m0 >> 11;          // batch
    const int kb_ = (m0 >> 6) & 31;    // 64-block within seq
    const size_t vrow0 = ((size_t)(b_ * 32 + kb_)) * 64;

    #pragma unroll
    for (int mt = 0; mt < 2; mt++) {
        size_t r0 = (size_t)m0 + mg * 32 + mt * 16 + g;
        int    t0 = (int)(r0 & 63);
        #pragma unroll
        for (int nb = 0; nb < 6; nb++) {
            int n0  = ng * 48 + nb * 8;
            int w   = n0 >> 6;
            int col = (n0 & 63) + 2 * tg;
            float v00 = acc[mt][nb][0], v01 = acc[mt][nb][1];
            float v10 = acc[mt][nb][2], v11 = acc[mt][nb][3];
            if (w == 0) {                       // QSCALE already folded into Wq
                size_t i0 = r0 * 32 + (col >> 1);
                g_qh[i0]       = pack_hi(v00, v01);
                g_ql[i0]       = pack_lo(v00, v01);
                g_qh[i0 + 256] = pack_hi(v10, v11);
                g_ql[i0 + 256] = pack_lo(v10, v11);
            } else if (w == 1) {
                size_t i0 = r0 * 32 + (col >> 1);
                g_kh[i0]       = pack_hi(v00, v01);
                g_kl[i0]       = pack_lo(v00, v01);
                g_kh[i0 + 256] = pack_hi(v10, v11);
                g_kl[i0 + 256] = pack_lo(v10, v11);
            } else {
                size_t iA = (vrow0 + col) * 64 + t0;
                size_t iB = (vrow0 + col + 1) * 64 + t0;
                __nv_bfloat16 h;
                h = __float2bfloat16(v00); g_vth[iA]     = h;
                g_vtl[iA]     = __float2bfloat16(v00 - __bfloat162float(h));
                h = __float2bfloat16(v01); g_vth[iB]     = h;
                g_vtl[iB]     = __float2bfloat16(v01 - __bfloat162float(h));
                h = __float2bfloat16(v10); g_vth[iA + 8] = h;
                g_vtl[iA + 8] = __float2bfloat16(v10 - __bfloat162float(h));
                h = __float2bfloat16(v11); g_vth[iB + 8] = h;
                g_vtl[iB + 8] = __float2bfloat16(v11 - __bfloat162float(h));
            }
        }
    }
}

// ---------------------------------------------------------------------------
// Tensor-core flash attention (unchanged from R8's passing version).
// CTA = 64 queries, 8 warps: mw = 16-row group, nw = 32-key half, split
// softmax merged once at the end. 2-stage cp.async K/V pipeline.
// ---------------------------------------------------------------------------
#define TILE  4608                      // bf16 elems per tile (64*72)
#define ATTN_SMEM_BYTES (10 * TILE * 2) // 92160

__global__ __launch_bounds__(256, 2) void attn_mma_kernel(float* __restrict__ out)
{
    extern __shared__ __nv_bfloat16 sm[];
    __nv_bfloat16* Qh = sm;
    __nv_bfloat16* Ql = sm + TILE;
    __nv_bfloat16* KV = sm + 2 * TILE;  // [2 bufs][Kh,Kl,Vth,Vtl]

    const int tid  = threadIdx.x;
    const int warp = tid >> 5;
    const int lane = tid & 31;
    const int g    = lane >> 2;
    const int tg   = lane & 3;
    const int mw   = warp & 3;
    const int nw   = warp >> 2;
    const int qb   = blockIdx.x;
    const int b    = blockIdx.y;
    const size_t base = (size_t)b * SEQ * NHEAD;
    const int q0   = qb * 64;

    const uint32_t smQh = smem_u32p(Qh);
    const uint32_t smKV = smem_u32p(KV);

    const int sr0 = tid >> 3;
    const int sc  = (tid & 7) * 16;

    const size_t rq = (size_t)b * SEQ + q0;
    {
        const char* qhs = (const char*)g_qh + rq * 128;
        const char* qls = (const char*)g_ql + rq * 128;
        cp16(smQh + sr0 * 144 + sc,                   qhs + sr0 * 128 + sc);
        cp16(smQh + (sr0 + 32) * 144 + sc,            qhs + (sr0 + 32) * 128 + sc);
        cp16(smQh + TILE * 2 + sr0 * 144 + sc,        qls + sr0 * 128 + sc);
        cp16(smQh + TILE * 2 + (sr0 + 32) * 144 + sc, qls + (sr0 + 32) * 128 + sc);
    }
    #define STAGE_KV(kb, buf) do {                                             \
        size_t rk_ = (size_t)b * SEQ + (size_t)(kb) * 64;                      \
        size_t rv_ = ((size_t)(b * 32 + (kb))) * 64;                           \
        uint32_t d0_ = smKV + (buf) * 4 * TILE * 2;                            \
        const char* s0_ = (const char*)g_kh  + rk_ * 128;                      \
        const char* s1_ = (const char*)g_kl  + rk_ * 128;                      \
        const char* s2_ = (const char*)g_vth + rv_ * 128;                      \
        const char* s3_ = (const char*)g_vtl + rv_ * 128;                      \
        _Pragma("unroll")                                                      \
        for (int i_ = 0; i_ < 2; i_++) {                                       \
            int r_ = sr0 + i_ * 32;                                            \
            uint32_t dd_ = d0_ + r_ * 144 + sc;                                \
            const size_t so_ = (size_t)r_ * 128 + sc;                          \
            cp16(dd_,                 s0_ + so_);                              \
            cp16(dd_ + 2 * TILE,      s1_ + so_);                              \
            cp16(dd_ + 4 * TILE,      s2_ + so_);                              \
            cp16(dd_ + 6 * TILE,      s3_ + so_);                              \
        }                                                                      \
    } while (0)

    STAGE_KV(0, 0);
    CP_COMMIT();

    float o[8][4];
    #pragma unroll
    for (int nb = 0; nb < 8; nb++)
        #pragma unroll
        for (int i = 0; i < 4; i++) o[nb][i] = 0.0f;
    float mrun[2] = {-1e30f, -1e30f};
    float lrun[2] = {0.0f, 0.0f};

    const uint32_t* Qh32 = (const uint32_t*)Qh;
    const uint32_t* Ql32 = (const uint32_t*)Ql;

    for (int kb = 0; kb <= qb; kb++) {
        if (kb > 0) __syncthreads();
        if (kb < qb) {
            STAGE_KV(kb + 1, (kb + 1) & 1);
            CP_COMMIT();
            CP_WAIT(1);
        } else {
            CP_WAIT(0);
        }
        __syncthreads();

        const uint32_t* Kh32  = (const uint32_t*)(KV + (kb & 1) * 4 * TILE);
        const uint32_t* Kl32  = Kh32 + TILE / 2;
        const uint32_t* Vth32 = Kh32 + TILE;
        const uint32_t* Vtl32 = Kh32 + 3 * TILE / 2;

        float s[4][4];
        #pragma unroll
        for (int nb = 0; nb < 4; nb++)
            #pragma unroll
            for (int i = 0; i < 4; i++) s[nb][i] = 0.0f;

        #pragma unroll
        for (int ks = 0; ks < 4; ks++) {
            uint32_t qh[4], ql[4];
            uint32_t o0 = (mw * 16 + g) * 36 + ks * 8 + tg;
            uint32_t o1 = o0 + 8 * 36;
            qh[0] = Qh32[o0]; qh[1] = Qh32[o1];
            qh[2] = Qh32[o0 + 4]; qh[3] = Qh32[o1 + 4];
            ql[0] = Ql32[o0]; ql[1] = Ql32[o1];
            ql[2] = Ql32[o0 + 4]; ql[3] = Ql32[o1 + 4];
            #pragma unroll
            for (int nb = 0; nb < 4; nb++) {
                uint32_t ob = (nw * 32 + nb * 8 + g) * 36 + ks * 8 + tg;
                uint32_t bh[2], bl[2];
                bh[0] = Kh32[ob]; bh[1] = Kh32[ob + 4];
                bl[0] = Kl32[ob]; bl[1] = Kl32[ob + 4];
                mma_bf16(s[nb], qh, bh);
                mma_bf16(s[nb], qh, bl);
                mma_bf16(s[nb], ql, bh);
            }
        }

        if (kb == qb) {
            int r0 = q0 + mw * 16 + g;
            #pragma unroll
            for (int nb = 0; nb < 4; nb++) {
                int col = kb * 64 + nw * 32 + nb * 8 + 2 * tg;
                if (col     > r0)     s[nb][0] = -1e30f;
                if (col + 1 > r0)     s[nb][1] = -1e30f;
                if (col     > r0 + 8) s[nb][2] = -1e30f;
                if (col + 1 > r0 + 8) s[nb][3] = -1e30f;
            }
        }

        float mx0 = -1e30f, mx1 = -1e30f;
        #pragma unroll
        for (int nb = 0; nb < 4; nb++) {
            mx0 = fmaxf(mx0, fmaxf(s[nb][0], s[nb][1]));
            mx1 = fmaxf(mx1, fmaxf(s[nb][2], s[nb][3]));
        }
        mx0 = fmaxf(mx0, __shfl_xor_sync(0xffffffffu, mx0, 1));
        mx0 = fmaxf(mx0, __shfl_xor_sync(0xffffffffu, mx0, 2));
        mx1 = fmaxf(mx1, __shfl_xor_sync(0xffffffffu, mx1, 1));
        mx1 = fmaxf(mx1, __shfl_xor_sync(0xffffffffu, mx1, 2));

        float mn0 = fmaxf(mrun[0], mx0);
        float mn1 = fmaxf(mrun[1], mx1);
        float corr0 = ex2(mrun[0] - mn0);
        float corr1 = ex2(mrun[1] - mn1);
        mrun[0] = mn0; mrun[1] = mn1;

        float ps0 = 0.0f, ps1 = 0.0f;
        #pragma unroll
        for (int nb = 0; nb < 4; nb++) {
            s[nb][0] = ex2(s[nb][0] - mn0);
            s[nb][1] = ex2(s[nb][1] - mn0);
            s[nb][2] = ex2(s[nb][2] - mn1);
            s[nb][3] = ex2(s[nb][3] - mn1);
            ps0 += s[nb][0] + s[nb][1];
            ps1 += s[nb][2] + s[nb][3];
        }
        ps0 += __shfl_xor_sync(0xffffffffu, ps0, 1);
        ps0 += __shfl_xor_sync(0xffffffffu, ps0, 2);
        ps1 += __shfl_xor_sync(0xffffffffu, ps1, 1);
        ps1 += __shfl_xor_sync(0xffffffffu, ps1, 2);
        lrun[0] = lrun[0] * corr0 + ps0;
        lrun[1] = lrun[1] * corr1 + ps1;

        #pragma unroll
        for (int nb = 0; nb < 8; nb++) {
            o[nb][0] *= corr0; o[nb][1] *= corr0;
            o[nb][2] *= corr1; o[nb][3] *= corr1;
        }

        #pragma unroll
        for (int ks = 0; ks < 2; ks++) {
            uint32_t ph[4], pl[4];
            ph[0] = pack_hi(s[2*ks][0],   s[2*ks][1]);
            ph[1] = pack_hi(s[2*ks][2],   s[2*ks][3]);
            ph[2] = pack_hi(s[2*ks+1][0], s[2*ks+1][1]);
            ph[3] = pack_hi(s[2*ks+1][2], s[2*ks+1][3]);
            pl[0] = pack_lo(s[2*ks][0],   s[2*ks][1]);
            pl[1] = pack_lo(s[2*ks][2],   s[2*ks][3]);
            pl[2] = pack_lo(s[2*ks+1][0], s[2*ks+1][1]);
            pl[3] = pack_lo(s[2*ks+1][2], s[2*ks+1][3]);
            #pragma unroll
            for (int nb = 0; nb < 8; nb++) {
                uint32_t ob = (nb * 8 + g) * 36 + nw * 16 + ks * 8 + tg;
                uint32_t vh[2], vl[2];
                vh[0] = Vth32[ob]; vh[1] = Vth32[ob + 4];
                vl[0] = Vtl32[ob]; vl[1] = Vtl32[ob + 4];
                mma_bf16(o[nb], ph, vh);
                mma_bf16(o[nb], ph, vl);
                mma_bf16(o[nb], pl, vh);
            }
        }
    }

    __syncthreads();
    float* Of = (float*)KV;               // 64 x 66 f32 (even stride)
    float* Ml = (float*)sm;
    const int r0l = mw * 16 + g;

    if (nw == 1) {
        if (tg == 0) {
            Ml[r0l]          = mrun[0];
            Ml[64 + r0l]     = lrun[0];
            Ml[r0l + 8]      = mrun[1];
            Ml[64 + r0l + 8] = lrun[1];
        }
        #pragma unroll
        for (int nb = 0; nb < 8; nb++) {
            int col = nb * 8 + 2 * tg;
            *(float2*)&Of[r0l * 66 + col]       = make_float2(o[nb][0], o[nb][1]);
            *(float2*)&Of[(r0l + 8) * 66 + col] = make_float2(o[nb][2], o[nb][3]);
        }
    }
    __syncthreads();
    if (nw == 0) {
        float m1a = Ml[r0l],     l1a = Ml[64 + r0l];
        float m1b = Ml[r0l + 8], l1b = Ml[64 + r0l + 8];
        float ma = fmaxf(mrun[0], m1a), mb = fmaxf(mrun[1], m1b);
        float c0a = ex2(mrun[0] - ma), c1a = ex2(m1a - ma);
        float c0b = ex2(mrun[1] - mb), c1b = ex2(m1b - mb);
        float ia = 1.0f / (c0a * lrun[0] + c1a * l1a);
        float ib = 1.0f / (c0b * lrun[1] + c1b * l1b);
        float* oa = out + base + (size_t)(q0 + r0l) * NHEAD;
        float* ob = out + base + (size_t)(q0 + r0l + 8) * NHEAD;
        #pragma unroll
        for (int nb = 0; nb < 8; nb++) {
            int col = nb * 8 + 2 * tg;
            float2 p1 = *(float2*)&Of[r0l * 66 + col];
            float2 p2 = *(float2*)&Of[(r0l + 8) * 66 + col];
            *(float2*)(oa + col) = make_float2((c0a * o[nb][0] + c1a * p1.x) * ia,
                                               (c0a * o[nb][1] + c1a * p1.y) * ia);
            *(float2*)(ob + col) = make_float2((c0b * o[nb][2] + c1b * p2.x) * ib,
                                               (c0b * o[nb][3] + c1b * p2.y) * ib);
        }
    }
}

// ---------------------------------------------------------------------------
extern "C" void kernel_launch(void* const* d_in, const int* in_sizes, int n_in,
                              void* d_out, int out_size)
{
    (void)in_sizes; (void)n_in; (void)out_size;
    const float* x  = (const float*)d_in[0];
    const float* Wk = (const float*)d_in[1];
    const float* Wq = (const float*)d_in[2];
    const float* Wv = (const float*)d_in[3];
    float* out = (float*)d_out;

    cudaFuncSetAttribute(attn_mma_kernel,
                         cudaFuncAttributeMaxDynamicSharedMemorySize,
                         ATTN_SMEM_BYTES);

    wsplit_kernel<<<dim3(768, 1, 1), 256>>>(Wk, Wq, Wv);
    qkv_mma_kernel<<<dim3(ROWS / 64, 1, 1), 256>>>(x, Wk, Wq, Wv);
    attn_mma_kernel<<<dim3(SEQ / 64, BATCH, 1), 256, ATTN_SMEM_BYTES>>>(out);
}

// round 17
// speedup vs baseline: 1.1204x; 1.1204x over previous
#include <cuda_runtime.h>
#include <cuda_bf16.h>
#include <cstdint>

#define SEQ   2048
#define EMB   1024
#define NHEAD 64
#define BATCH 8
#define ROWS  (BATCH*SEQ)   // 16384

// Split-bf16 scratch (allocation-free device globals, 16B-aligned for cp.async).
__device__ __align__(16) uint32_t      g_qh[(size_t)ROWS * 32], g_ql[(size_t)ROWS * 32];
__device__ __align__(16) uint32_t      g_kh[(size_t)ROWS * 32], g_kl[(size_t)ROWS * 32];
__device__ __align__(16) __nv_bfloat16 g_vth[(size_t)ROWS * 64], g_vtl[(size_t)ROWS * 64];
// Pre-split weights, chunk-tiled: [c][row r][kk], r<192 = hi(n=r), r>=192 = lo.
__device__ __align__(16) __nv_bfloat16 g_wsp[(size_t)32 * 384 * 32];

#define QSCALE 0.1803368801111243f   // 0.125 * log2(e): base-2 softmax

// ---------------------------------------------------------------------------
// Helpers
// ---------------------------------------------------------------------------
__device__ __forceinline__ void split2(float vx, float vy,
                                       uint32_t& hi, uint32_t& lo)
{
    __nv_bfloat16 hx = __float2bfloat16(vx);
    __nv_bfloat16 hy = __float2bfloat16(vy);
    __nv_bfloat16 lx = __float2bfloat16(vx - __bfloat162float(hx));
    __nv_bfloat16 ly = __float2bfloat16(vy - __bfloat162float(hy));
    hi = ((uint32_t)__bfloat16_as_ushort(hy) << 16) | __bfloat16_as_ushort(hx);
    lo = ((uint32_t)__bfloat16_as_ushort(ly) << 16) | __bfloat16_as_ushort(lx);
}

__device__ __forceinline__ void mma_bf16(float* c, const uint32_t* a,
                                         const uint32_t* b)
{
    asm volatile(
        "mma.sync.aligned.m16n8k16.row.col.f32.bf16.bf16.f32 "
        "{%0,%1,%2,%3}, {%4,%5,%6,%7}, {%8,%9}, {%0,%1,%2,%3};"
        : "+f"(c[0]), "+f"(c[1]), "+f"(c[2]), "+f"(c[3])
        : "r"(a[0]), "r"(a[1]), "r"(a[2]), "r"(a[3]), "r"(b[0]), "r"(b[1]));
}

// ldmatrix x4: four 8x8 bf16 mats; lane L supplies the row address for
// mat L/8, row L%8. Byte addresses in shared space.
__device__ __forceinline__ void ldsm4(uint32_t* r, uint32_t addr)
{
    asm volatile(
        "ldmatrix.sync.aligned.m8n8.x4.shared.b16 {%0,%1,%2,%3}, [%4];"
        : "=r"(r[0]), "=r"(r[1]), "=r"(r[2]), "=r"(r[3]) : "r"(addr));
}

__device__ __forceinline__ float ex2(float x) {
    float y;
    asm("ex2.approx.f32 %0, %1;" : "=f"(y) : "f"(x));
    return y;
}

__device__ __forceinline__ uint32_t pack_hi(float a, float b) {
    return ((uint32_t)__bfloat16_as_ushort(__float2bfloat16(b)) << 16) |
           __bfloat16_as_ushort(__float2bfloat16(a));
}
__device__ __forceinline__ uint32_t pack_lo(float a, float b) {
    float ra = a - __bfloat162float(__float2bfloat16(a));
    float rb = b - __bfloat162float(__float2bfloat16(b));
    return pack_hi(ra, rb);
}

__device__ __forceinline__ uint32_t smem_u32p(const void* p) {
    uint32_t a;
    asm("{ .reg .u64 t; cvta.to.shared.u64 t, %1; cvt.u32.u64 %0, t; }"
        : "=r"(a) : "l"(p));
    return a;
}
__device__ __forceinline__ void cp16(uint32_t dst, const void* src) {
    asm volatile("cp.async.ca.shared.global [%0], [%1], 16;"
                 :: "r"(dst), "l"(src));
}
#define CP_COMMIT()  asm volatile("cp.async.commit_group;" ::: "memory")
#define CP_WAIT(n)   asm volatile("cp.async.wait_group %0;" :: "n"(n) : "memory")

// ---------------------------------------------------------------------------
// Prologue: split W -> chunk-tiled split-bf16, QSCALE folded. u32-pair
// stores (coalesced along kk).
// ---------------------------------------------------------------------------
__global__ __launch_bounds__(256) void wsplit_kernel(
    const float* __restrict__ Wk,
    const float* __restrict__ Wq,
    const float* __restrict__ Wv)
{
    int idx = blockIdx.x * 256 + threadIdx.x;   // 98304 = 32c * 192n * 16kkp
    int kkp = idx & 15;
    int n   = (idx >> 4) % 192;
    int c   = idx / 3072;
    int k0  = c * 32 + kkp * 2;
    const float* Wp = (n < 64) ? Wq : ((n < 128) ? Wk : Wv);
    float v0 = Wp[(size_t)k0 * NHEAD + (n & 63)];
    float v1 = Wp[(size_t)(k0 + 1) * NHEAD + (n & 63)];
    if (n < 64) { v0 *= QSCALE; v1 *= QSCALE; }
    uint32_t h, l;
    split2(v0, v1, h, l);
    *(uint32_t*)&g_wsp[((size_t)c * 384 + n) * 32 + kkp * 2]       = h;
    *(uint32_t*)&g_wsp[((size_t)c * 384 + 192 + n) * 32 + kkp * 2] = l;
}

// ---------------------------------------------------------------------------
// QKV projection via mma.sync bf16 (2-term split). M=64/CTA (grid 256),
// N=192 fused, K in 32-wide chunks. x register-prefetched + split in-kernel;
// W pre-split, cp.async double-buffered. All fragment loads via ldmatrix.x4.
// A rows stride 40 bf16 (80B), B rows 40 bf16 -> conflict-free LDSM phases.
// ---------------------------------------------------------------------------
__global__ __launch_bounds__(256, 2) void qkv_mma_kernel(
    const float* __restrict__ x,
    const float* __restrict__ Wk,
    const float* __restrict__ Wq,
    const float* __restrict__ Wv)
{
    __shared__ __nv_bfloat16 Ah[64 * 40], Al[64 * 40];    // 10240 B
    __shared__ __nv_bfloat16 Bsm[2 * 384 * 40];           // 61440 B

    const int tid  = threadIdx.x;
    const int warp = tid >> 5;
    const int lane = tid & 31;
    const int g    = lane >> 2;
    const int tg   = lane & 3;
    const int mg   = warp & 1;        // 32-row half
    const int ng   = warp >> 1;       // 48-col group
    const int m0   = blockIdx.x * 64;

    const uint32_t smB  = smem_u32p(Bsm);
    const uint32_t smAh = smem_u32p(Ah);
    const uint32_t smAl = smem_u32p(Al);

    // ldmatrix lane geometry
    const uint32_t a_rc = (uint32_t)(lane & 15) * 80 + ((lane >> 4) << 4);  // A-type
    const uint32_t b_rc = (uint32_t)((lane & 7) + ((lane >> 4) << 3)) * 80 +
                          (((lane >> 3) & 1) << 4);                          // B-type

    float acc[2][6][4];
    #pragma unroll
    for (int mt = 0; mt < 2; mt++)
        #pragma unroll
        for (int nb = 0; nb < 6; nb++)
            #pragma unroll
            for (int i = 0; i < 4; i++) acc[mt][nb][i] = 0.0f;

    float4 xa[2];
    const int xr  = tid >> 3;
    const int xc4 = (tid & 7) * 4;

    #define LOAD_X(chunk) do {                                                 \
        int k0_ = (chunk) * 32;                                                \
        xa[0] = *(const float4*)(x + (size_t)(m0 + xr) * EMB + k0_ + xc4);     \
        xa[1] = *(const float4*)(x + (size_t)(m0 + xr + 32) * EMB + k0_ + xc4);\
    } while (0)

    // B staging: 384 rows x 64B = 1536 16B-chunks, 6 per thread
    const int br = tid >> 2;
    const int bp = (tid & 3) * 16;
    #define STAGE_B(chunk, buf) do {                                           \
        const char* src_ = (const char*)g_wsp + (size_t)(chunk) * 384 * 64;    \
        uint32_t d_ = smB + (buf) * 30720;                                     \
        _Pragma("unroll")                                                      \
        for (int j_ = 0; j_ < 6; j_++) {                                       \
            int r_ = br + j_ * 64;                                             \
            cp16(d_ + r_ * 80 + bp, src_ + (size_t)r_ * 64 + bp);              \
        }                                                                      \
    } while (0)

    STAGE_B(0, 0);
    CP_COMMIT();
    LOAD_X(0);

    for (int chunk = 0; chunk < 32; chunk++) {
        __syncthreads();

        #pragma unroll
        for (int i = 0; i < 2; i++) {
            int r = xr + i * 32;
            uint32_t h0, l0, h1, l1;
            split2(xa[i].x, xa[i].y, h0, l0);
            split2(xa[i].z, xa[i].w, h1, l1);
            uint32_t off = r * 40 + xc4;
            *(uint32_t*)(Ah + off)     = h0;
            *(uint32_t*)(Ah + off + 2) = h1;
            *(uint32_t*)(Al + off)     = l0;
            *(uint32_t*)(Al + off + 2) = l1;
        }
        if (chunk < 31) {
            STAGE_B(chunk + 1, (chunk + 1) & 1);
            CP_COMMIT();
            CP_WAIT(1);
        } else {
            CP_WAIT(0);
        }
        __syncthreads();

        if (chunk < 31) LOAD_X(chunk + 1);

        const uint32_t bB = smB + (chunk & 1) * 30720;

        #pragma unroll
        for (int ks = 0; ks < 2; ks++) {
            uint32_t ah[2][4], al2[2][4];
            #pragma unroll
            for (int mt = 0; mt < 2; mt++) {
                uint32_t aa = (mg * 32 + mt * 16) * 80 + a_rc + ks * 32;
                ldsm4(ah[mt],  smAh + aa);
                ldsm4(al2[mt], smAl + aa);
            }
            #pragma unroll
            for (int nbp = 0; nbp < 3; nbp++) {
                uint32_t bh[4], bl[4];
                uint32_t ba = bB + (ng * 48 + nbp * 16) * 80 + b_rc + ks * 32;
                ldsm4(bh, ba);
                ldsm4(bl, ba + 15360);       // +192 rows * 80B
                #pragma unroll
                for (int mt = 0; mt < 2; mt++) {
                    mma_bf16(acc[mt][2*nbp],   ah[mt],  &bh[0]);
                    mma_bf16(acc[mt][2*nbp],   ah[mt],  &bl[0]);
                    mma_bf16(acc[mt][2*nbp],   al2[mt], &bh[0]);
                    mma_bf16(acc[mt][2*nbp+1], ah[mt],  &bh[2]);
                    mma_bf16(acc[mt][2*nbp+1], ah[mt],  &bl[2]);
                    mma_bf16(acc[mt][2*nbp+1], al2[mt], &bh[2]);
                }
            }
        }
    }

    // ---- epilogue: write split-bf16 q/k (row-major) and v (transposed) ----
    const int b_  = m0 >> 11;
    const int kb_ = (m0 >> 6) & 31;
    const size_t vrow0 = ((size_t)(b_ * 32 + kb_)) * 64;

    #pragma unroll
    for (int mt = 0; mt < 2; mt++) {
        size_t r0 = (size_t)m0 + mg * 32 + mt * 16 + g;
        int    t0 = (int)(r0 & 63);
        #pragma unroll
        for (int nb = 0; nb < 6; nb++) {
            int n0  = ng * 48 + nb * 8;
            int w   = n0 >> 6;
            int col = (n0 & 63) + 2 * tg;
            float v00 = acc[mt][nb][0], v01 = acc[mt][nb][1];
            float v10 = acc[mt][nb][2], v11 = acc[mt][nb][3];
            if (w == 0) {
                size_t i0 = r0 * 32 + (col >> 1);
                g_qh[i0]       = pack_hi(v00, v01);
                g_ql[i0]       = pack_lo(v00, v01);
                g_qh[i0 + 256] = pack_hi(v10, v11);
                g_ql[i0 + 256] = pack_lo(v10, v11);
            } else if (w == 1) {
                size_t i0 = r0 * 32 + (col >> 1);
                g_kh[i0]       = pack_hi(v00, v01);
                g_kl[i0]       = pack_lo(v00, v01);
                g_kh[i0 + 256] = pack_hi(v10, v11);
                g_kl[i0 + 256] = pack_lo(v10, v11);
            } else {
                size_t iA = (vrow0 + col) * 64 + t0;
                size_t iB = (vrow0 + col + 1) * 64 + t0;
                __nv_bfloat16 h;
                h = __float2bfloat16(v00); g_vth[iA]     = h;
                g_vtl[iA]     = __float2bfloat16(v00 - __bfloat162float(h));
                h = __float2bfloat16(v01); g_vth[iB]     = h;
                g_vtl[iB]     = __float2bfloat16(v01 - __bfloat162float(h));
                h = __float2bfloat16(v10); g_vth[iA + 8] = h;
                g_vtl[iA + 8] = __float2bfloat16(v10 - __bfloat162float(h));
                h = __float2bfloat16(v11); g_vth[iB + 8] = h;
                g_vtl[iB + 8] = __float2bfloat16(v11 - __bfloat162float(h));
            }
        }
    }
}

// ---------------------------------------------------------------------------
// Tensor-core flash attention. CTA = 64 queries, 8 warps (mw 16-row group,
// nw 32-key half), split softmax merged at end, 2-stage cp.async pipeline.
// All fragment loads via ldmatrix.x4 (rows 144B stride -> conflict-free).
// ---------------------------------------------------------------------------
#define TILE  4608                      // bf16 elems per tile (64*72)
#define ATTN_SMEM_BYTES (10 * TILE * 2) // 92160

__global__ __launch_bounds__(256, 2) void attn_mma_kernel(float* __restrict__ out)
{
    extern __shared__ __nv_bfloat16 sm[];
    __nv_bfloat16* Qh = sm;
    __nv_bfloat16* KV = sm + 2 * TILE;

    const int tid  = threadIdx.x;
    const int warp = tid >> 5;
    const int lane = tid & 31;
    const int g    = lane >> 2;
    const int tg   = lane & 3;
    const int mw   = warp & 3;
    const int nw   = warp >> 2;
    const int qb   = blockIdx.x;
    const int b    = blockIdx.y;
    const size_t base = (size_t)b * SEQ * NHEAD;
    const int q0   = qb * 64;

    const uint32_t smQh = smem_u32p(Qh);
    const uint32_t smKV = smem_u32p(KV);

    // ldmatrix lane geometry (byte offsets, 144B row stride)
    const uint32_t a_rc = (uint32_t)(lane & 15) * 144 + ((lane >> 4) << 4);
    const uint32_t b_rc = (uint32_t)((lane & 7) + ((lane >> 4) << 3)) * 144 +
                          (((lane >> 3) & 1) << 4);

    const int sr0 = tid >> 3;
    const int sc  = (tid & 7) * 16;

    const size_t rq = (size_t)b * SEQ + q0;
    {
        const char* qhs = (const char*)g_qh + rq * 128;
        const char* qls = (const char*)g_ql + rq * 128;
        cp16(smQh + sr0 * 144 + sc,                   qhs + sr0 * 128 + sc);
        cp16(smQh + (sr0 + 32) * 144 + sc,            qhs + (sr0 + 32) * 128 + sc);
        cp16(smQh + TILE * 2 + sr0 * 144 + sc,        qls + sr0 * 128 + sc);
        cp16(smQh + TILE * 2 + (sr0 + 32) * 144 + sc, qls + (sr0 + 32) * 128 + sc);
    }
    #define STAGE_KV(kb, buf) do {                                             \
        size_t rk_ = (size_t)b * SEQ + (size_t)(kb) * 64;                      \
        size_t rv_ = ((size_t)(b * 32 + (kb))) * 64;                           \
        uint32_t d0_ = smKV + (buf) * 4 * TILE * 2;                            \
        const char* s0_ = (const char*)g_kh  + rk_ * 128;                      \
        const char* s1_ = (const char*)g_kl  + rk_ * 128;                      \
        const char* s2_ = (const char*)g_vth + rv_ * 128;                      \
        const char* s3_ = (const char*)g_vtl + rv_ * 128;                      \
        _Pragma("unroll")                                                      \
        for (int i_ = 0; i_ < 2; i_++) {                                       \
            int r_ = sr0 + i_ * 32;                                            \
            uint32_t dd_ = d0_ + r_ * 144 + sc;                                \
            const size_t so_ = (size_t)r_ * 128 + sc;                          \
            cp16(dd_,                 s0_ + so_);                              \
            cp16(dd_ + 2 * TILE,      s1_ + so_);                              \
            cp16(dd_ + 4 * TILE,      s2_ + so_);                              \
            cp16(dd_ + 6 * TILE,      s3_ + so_);                              \
        }                                                                      \
    } while (0)

    STAGE_KV(0, 0);
    CP_COMMIT();

    float o[8][4];
    #pragma unroll
    for (int nb = 0; nb < 8; nb++)
        #pragma unroll
        for (int i = 0; i < 4; i++) o[nb][i] = 0.0f;
    float mrun[2] = {-1e30f, -1e30f};
    float lrun[2] = {0.0f, 0.0f};

    for (int kb = 0; kb <= qb; kb++) {
        if (kb > 0) __syncthreads();
        if (kb < qb) {
            STAGE_KV(kb + 1, (kb + 1) & 1);
            CP_COMMIT();
            CP_WAIT(1);
        } else {
            CP_WAIT(0);
        }
        __syncthreads();

        const uint32_t kvb = smKV + (kb & 1) * 4 * TILE * 2;   // Kh base (bytes)

        // ---- S = Q K^T over this warp's 32-key half (3-term split) ----
        float s[4][4];
        #pragma unroll
        for (int nb = 0; nb < 4; nb++)
            #pragma unroll
            for (int i = 0; i < 4; i++) s[nb][i] = 0.0f;

        #pragma unroll
        for (int ks = 0; ks < 4; ks++) {
            uint32_t qh[4], ql[4];
            uint32_t qa = smQh + mw * 16 * 144 + a_rc + ks * 32;
            ldsm4(qh, qa);
            ldsm4(ql, qa + 2 * TILE);
            #pragma unroll
            for (int nbp = 0; nbp < 2; nbp++) {
                uint32_t kh[4], kl[4];
                uint32_t ka = kvb + (nw * 32 + nbp * 16) * 144 + b_rc + ks * 32;
                ldsm4(kh, ka);
                ldsm4(kl, ka + 2 * TILE);
                mma_bf16(s[2*nbp],   qh, &kh[0]);
                mma_bf16(s[2*nbp],   qh, &kl[0]);
                mma_bf16(s[2*nbp],   ql, &kh[0]);
                mma_bf16(s[2*nbp+1], qh, &kh[2]);
                mma_bf16(s[2*nbp+1], qh, &kl[2]);
                mma_bf16(s[2*nbp+1], ql, &kh[2]);
            }
        }

        if (kb == qb) {
            int r0 = q0 + mw * 16 + g;
            #pragma unroll
            for (int nb = 0; nb < 4; nb++) {
                int col = kb * 64 + nw * 32 + nb * 8 + 2 * tg;
                if (col     > r0)     s[nb][0] = -1e30f;
                if (col + 1 > r0)     s[nb][1] = -1e30f;
                if (col     > r0 + 8) s[nb][2] = -1e30f;
                if (col + 1 > r0 + 8) s[nb][3] = -1e30f;
            }
        }

        float mx0 = -1e30f, mx1 = -1e30f;
        #pragma unroll
        for (int nb = 0; nb < 4; nb++) {
            mx0 = fmaxf(mx0, fmaxf(s[nb][0], s[nb][1]));
            mx1 = fmaxf(mx1, fmaxf(s[nb][2], s[nb][3]));
        }
        mx0 = fmaxf(mx0, __shfl_xor_sync(0xffffffffu, mx0, 1));
        mx0 = fmaxf(mx0, __shfl_xor_sync(0xffffffffu, mx0, 2));
        mx1 = fmaxf(mx1, __shfl_xor_sync(0xffffffffu, mx1, 1));
        mx1 = fmaxf(mx1, __shfl_xor_sync(0xffffffffu, mx1, 2));

        float mn0 = fmaxf(mrun[0], mx0);
        float mn1 = fmaxf(mrun[1], mx1);
        float corr0 = ex2(mrun[0] - mn0);
        float corr1 = ex2(mrun[1] - mn1);
        mrun[0] = mn0; mrun[1] = mn1;

        float ps0 = 0.0f, ps1 = 0.0f;
        #pragma unroll
        for (int nb = 0; nb < 4; nb++) {
            s[nb][0] = ex2(s[nb][0] - mn0);
            s[nb][1] = ex2(s[nb][1] - mn0);
            s[nb][2] = ex2(s[nb][2] - mn1);
            s[nb][3] = ex2(s[nb][3] - mn1);
            ps0 += s[nb][0] + s[nb][1];
            ps1 += s[nb][2] + s[nb][3];
        }
        ps0 += __shfl_xor_sync(0xffffffffu, ps0, 1);
        ps0 += __shfl_xor_sync(0xffffffffu, ps0, 2);
        ps1 += __shfl_xor_sync(0xffffffffu, ps1, 1);
        ps1 += __shfl_xor_sync(0xffffffffu, ps1, 2);
        lrun[0] = lrun[0] * corr0 + ps0;
        lrun[1] = lrun[1] * corr1 + ps1;

        #pragma unroll
        for (int nb = 0; nb < 8; nb++) {
            o[nb][0] *= corr0; o[nb][1] *= corr0;
            o[nb][2] *= corr1; o[nb][3] *= corr1;
        }

        // ---- O += P V ----
        #pragma unroll
        for (int ks = 0; ks < 2; ks++) {
            uint32_t ph[4], pl[4];
            ph[0] = pack_hi(s[2*ks][0],   s[2*ks][1]);
            ph[1] = pack_hi(s[2*ks][2],   s[2*ks][3]);
            ph[2] = pack_hi(s[2*ks+1][0], s[2*ks+1][1]);
            ph[3] = pack_hi(s[2*ks+1][2], s[2*ks+1][3]);
            pl[0] = pack_lo(s[2*ks][0],   s[2*ks][1]);
            pl[1] = pack_lo(s[2*ks][2],   s[2*ks][3]);
            pl[2] = pack_lo(s[2*ks+1][0], s[2*ks+1][1]);
            pl[3] = pack_lo(s[2*ks+1][2], s[2*ks+1][3]);
            #pragma unroll
            for (int nbp = 0; nbp < 4; nbp++) {
                uint32_t vh[4], vl[4];
                uint32_t va = kvb + 4 * TILE + (nbp * 16) * 144 + b_rc +
                              nw * 64 + ks * 32;
                ldsm4(vh, va);
                ldsm4(vl, va + 2 * TILE);
                mma_bf16(o[2*nbp],   ph, &vh[0]);
                mma_bf16(o[2*nbp],   ph, &vl[0]);
                mma_bf16(o[2*nbp],   pl, &vh[0]);
                mma_bf16(o[2*nbp+1], ph, &vh[2]);
                mma_bf16(o[2*nbp+1], ph, &vl[2]);
                mma_bf16(o[2*nbp+1], pl, &vh[2]);
            }
        }
    }

    // ---- split-softmax merge across the two key halves + store ----
    __syncthreads();
    float* Of = (float*)KV;               // 64 x 66 f32 (even stride)
    float* Ml = (float*)sm;
    const int r0l = mw * 16 + g;

    if (nw == 1) {
        if (tg == 0) {
            Ml[r0l]          = mrun[0];
            Ml[64 + r0l]     = lrun[0];
            Ml[r0l + 8]      = mrun[1];
            Ml[64 + r0l + 8] = lrun[1];
        }
        #pragma unroll
        for (int nb = 0; nb < 8; nb++) {
            int col = nb * 8 + 2 * tg;
            *(float2*)&Of[r0l * 66 + col]       = make_float2(o[nb][0], o[nb][1]);
            *(float2*)&Of[(r0l + 8) * 66 + col] = make_float2(o[nb][2], o[nb][3]);
        }
    }
    __syncthreads();
    if (nw == 0) {
        float m1a = Ml[r0l],     l1a = Ml[64 + r0l];
        float m1b = Ml[r0l + 8], l1b = Ml[64 + r0l + 8];
        float ma = fmaxf(mrun[0], m1a), mb = fmaxf(mrun[1], m1b);
        float c0a = ex2(mrun[0] - ma), c1a = ex2(m1a - ma);
        float c0b = ex2(mrun[1] - mb), c1b = ex2(m1b - mb);
        float ia = 1.0f / (c0a * lrun[0] + c1a * l1a);
        float ib = 1.0f / (c0b * lrun[1] + c1b * l1b);
        float* oa = out + base + (size_t)(q0 + r0l) * NHEAD;
        float* ob = out + base + (size_t)(q0 + r0l + 8) * NHEAD;
        #pragma unroll
        for (int nb = 0; nb < 8; nb++) {
            int col = nb * 8 + 2 * tg;
            float2 p1 = *(float2*)&Of[r0l * 66 + col];
            float2 p2 = *(float2*)&Of[(r0l + 8) * 66 + col];
            *(float2*)(oa + col) = make_float2((c0a * o[nb][0] + c1a * p1.x) * ia,
                                               (c0a * o[nb][1] + c1a * p1.y) * ia);
            *(float2*)(ob + col) = make_float2((c0b * o[nb][2] + c1b * p2.x) * ib,
                                               (c0b * o[nb][3] + c1b * p2.y) * ib);
        }
    }
}

// ---------------------------------------------------------------------------
extern "C" void kernel_launch(void* const* d_in, const int* in_sizes, int n_in,
                              void* d_out, int out_size)
{
    (void)in_sizes; (void)n_in; (void)out_size;
    const float* x  = (const float*)d_in[0];
    const float* Wk = (const float*)d_in[1];
    const float* Wq = (const float*)d_in[2];
    const float* Wv = (const float*)d_in[3];
    float* out = (float*)d_out;

    cudaFuncSetAttribute(attn_mma_kernel,
                         cudaFuncAttributeMaxDynamicSharedMemorySize,
                         ATTN_SMEM_BYTES);

    wsplit_kernel<<<dim3(384, 1, 1), 256>>>(Wk, Wq, Wv);
    qkv_mma_kernel<<<dim3(ROWS / 64, 1, 1), 256>>>(x, Wk, Wq, Wv);
    attn_mma_kernel<<<dim3(SEQ / 64, BATCH, 1), 256, ATTN_SMEM_BYTES>>>(out);
}